// round 14
// baseline (speedup 1.0000x reference)
#include <cuda_runtime.h>
#include <cuda_fp16.h>
#include <math.h>
#include <stdint.h>

#define DIMN 2048
#define BATCH 4
#define LQ    4096
#define KC    576
#define KT    4672          // KC + LQ
#define KTP   4864          // padded N for the S GEMM (38*128)

typedef __half h16;

// ---------------------------------------------------------------------------
// Scratch (__device__ globals — zero-initialized; K rows [KT,KTP) stay 0)
// Fully single-pass fp16 scheme (calibrated error ~6e-4 < 1e-3).
// ---------------------------------------------------------------------------
__device__ h16 g_ch [(size_t)BATCH*LQ*DIMN];   // chunk (fp16)
__device__ h16 g_wqh[(size_t)DIMN*DIMN];
__device__ h16 g_wkh[(size_t)DIMN*DIMN];
__device__ h16 g_wvh[(size_t)DIMN*DIMN];
__device__ h16 g_woh[(size_t)DIMN*DIMN];
__device__ h16 g_qh [(size_t)BATCH*LQ*DIMN];
__device__ h16 g_kh [(size_t)BATCH*KTP*DIMN];
__device__ h16 g_vh [(size_t)BATCH*DIMN*KT];   // V^T [b][d][kt]
__device__ float g_s [(size_t)BATCH*LQ*KTP];
__device__ h16 g_ph [(size_t)BATCH*LQ*KT];
__device__ h16 g_ah [(size_t)BATCH*LQ*DIMN];

// ---------------------------------------------------------------------------
// helpers
// ---------------------------------------------------------------------------
__device__ __forceinline__ uint32_t s2u(const void* p) {
    uint32_t a;
    asm("{ .reg .u64 t; cvta.to.shared.u64 t, %1; cvt.u32.u64 %0, t; }" : "=r"(a) : "l"(p));
    return a;
}
__device__ __forceinline__ void cpa16(uint32_t d, const void* s) {
    asm volatile("cp.async.cg.shared.global [%0], [%1], 16;" :: "r"(d), "l"(s));
}
#define CP_COMMIT() asm volatile("cp.async.commit_group;" ::: "memory")
#define CP_WAIT1()  asm volatile("cp.async.wait_group 1;" ::: "memory")
#define CP_WAIT0()  asm volatile("cp.async.wait_group 0;" ::: "memory")

#define LDSM4(r, a) \
    asm volatile("ldmatrix.sync.aligned.m8n8.x4.shared.b16 {%0,%1,%2,%3}, [%4];" \
                 : "=r"((r)[0]), "=r"((r)[1]), "=r"((r)[2]), "=r"((r)[3]) : "r"(a))

__device__ __forceinline__ void mma16816(float* d, const uint32_t* a,
                                         uint32_t b0, uint32_t b1) {
    asm volatile(
        "mma.sync.aligned.m16n8k16.row.col.f32.f16.f16.f32 "
        "{%0,%1,%2,%3}, {%4,%5,%6,%7}, {%8,%9}, {%0,%1,%2,%3};"
        : "+f"(d[0]), "+f"(d[1]), "+f"(d[2]), "+f"(d[3])
        : "r"(a[0]), "r"(a[1]), "r"(a[2]), "r"(a[3]), "r"(b0), "r"(b1));
}

__device__ __forceinline__ uint32_t round2h(float x0, float x1) {
    __half2 hp = __floats2half2_rn(x0, x1);
    return *reinterpret_cast<uint32_t*>(&hp);
}

// ---------------------------------------------------------------------------
// fp16 single-pass mma.sync GEMM: C tile 128x128, BK=32, 3-stage cp.async
// pipeline, ONE __syncthreads per k-chunk. C = A·B^T, fp32 accum.
// A[M,K], B[N,K] row-major (NT).
// OUTM: 0 fp32 out, 1 fp16 out.
// BIASM: 0 none, 1 bias[col], 2 bias[row]
// TRI:  0 none, 1 = skip block if col0 >= KC+row0+BMT or col0 >= KT (S GEMM),
//       2 = clamp K loop to KC+row0+BMT (AV GEMM; heavy rows scheduled first)
// ---------------------------------------------------------------------------
#define BMT 128
#define BNT 128
#define BKT 32
#define APAD 40                          // fp16 row stride (32+8) -> 80B
#define TILE_B (128 * APAD * 2)          // 10240 bytes per tile
#define STAGE_B (2 * TILE_B)             // A|B = 20480
#define SMEM_MMA (3 * STAGE_B)           // 61440 bytes (3 stages) -> 2 CTAs/SM

template<int OUTM, int BIASM, int TRI>
__global__ __launch_bounds__(256, 2)
void gemm_mma(const h16* __restrict__ Ah,
              const h16* __restrict__ Bh,
              const float* __restrict__ bias,
              float* __restrict__ Cf, h16* __restrict__ Ch,
              int K, int lda, int ldb, int ldc,
              long long sA, long long sB, long long sC)
{
    // TRI==2: reverse row order so the heaviest (longest-K) CTAs start first
    const int row0 = (TRI == 2 ? (int)(gridDim.y - 1 - blockIdx.y) : (int)blockIdx.y) * BMT;
    const int col0 = blockIdx.x * BNT;
    if (TRI == 1 && (col0 >= KC + row0 + BMT || col0 >= KT)) return; // masked / pad tile

    extern __shared__ h16 sm[];
    const uint32_t smb = s2u(sm);
    const int tid  = threadIdx.x;
    const int lane = tid & 31, warp = tid >> 5;
    const int wm = warp & 1, wn = warp >> 1;    // warp grid 2 (M) x 4 (N)
    const size_t zA = (size_t)blockIdx.z * sA;
    const size_t zB = (size_t)blockIdx.z * sB;
    const size_t zC = (size_t)blockIdx.z * sC;

    int kchunks = K / BKT;
    if (TRI == 2) {
        int lim = (KC + row0 + BMT) / BKT;      // multiple of 32 by construction
        if (lim < kchunks) kchunks = lim;
    }

    // cp.async mapping: rows (tid>>2) and (tid>>2)+64, 16B chunk (tid&3)*8
    const int lrow = tid >> 2;
    const int lcol = (tid & 3) * 8;
    const uint32_t o1 = (lrow * APAD + lcol) * 2;
    const uint32_t o2 = ((lrow + 64) * APAD + lcol) * 2;

    auto issue = [&](int kc, int st) {
        const size_t ao = zA + (size_t)(row0 + lrow) * lda + (size_t)kc * BKT + lcol;
        const size_t bo = zB + (size_t)(col0 + lrow) * ldb + (size_t)kc * BKT + lcol;
        const uint32_t base = smb + st * STAGE_B;
        cpa16(base + o1,          Ah + ao);
        cpa16(base + o2,          Ah + ao + (size_t)64 * lda);
        cpa16(base + TILE_B + o1, Bh + bo);
        cpa16(base + TILE_B + o2, Bh + bo + (size_t)64 * ldb);
    };

    float acc[4][4][4];
#pragma unroll
    for (int i = 0; i < 4; i++)
#pragma unroll
        for (int j = 0; j < 4; j++)
#pragma unroll
            for (int e = 0; e < 4; e++) acc[i][j][e] = 0.f;

    // ldmatrix per-thread address components
    const int am = wm * 64 + (lane & 15);
    const int ak = (lane >> 4) * 8;
    const int bn = wn * 32 + (lane & 15);

    // prologue: fill 2 of the 3 stages
    issue(0, 0); CP_COMMIT();
    if (kchunks > 1) { issue(1, 1); CP_COMMIT(); }

    int st = 0;
    for (int kc = 0; kc < kchunks; ++kc) {
        if (kc + 1 < kchunks) CP_WAIT1(); else CP_WAIT0();
        __syncthreads();   // also covers the WAR hazard for stage (kc+2)%3

        if (kc + 2 < kchunks) {
            int st2 = st + 2; if (st2 >= 3) st2 -= 3;
            issue(kc + 2, st2);
            CP_COMMIT();
        }

        const uint32_t ah_ = smb + st * STAGE_B;
        const uint32_t bh_ = ah_ + TILE_B;
#pragma unroll
        for (int ks = 0; ks < 2; ks++) {
            uint32_t af[4][4], bh[2][4];
#pragma unroll
            for (int mt = 0; mt < 4; mt++)
                LDSM4(af[mt], ah_ + (((am + mt * 16) * APAD) + ks * 16 + ak) * 2);
#pragma unroll
            for (int pr = 0; pr < 2; pr++)
                LDSM4(bh[pr], bh_ + (((bn + pr * 16) * APAD) + ks * 16 + ak) * 2);
#pragma unroll
            for (int mt = 0; mt < 4; mt++)
#pragma unroll
                for (int nt = 0; nt < 4; nt++)
                    mma16816(acc[mt][nt], af[mt],
                             bh[nt >> 1][nt & 1], bh[nt >> 1][(nt & 1) + 2]);
        }
        if (++st == 3) st = 0;
    }

    // epilogue
    const int crow = lane >> 2;
    const int ccol = (lane & 3) * 2;
#pragma unroll
    for (int mt = 0; mt < 4; mt++) {
        const size_t r0g = (size_t)row0 + wm * 64 + mt * 16 + crow;
#pragma unroll
        for (int nt = 0; nt < 4; nt++) {
            const int cg = col0 + wn * 32 + nt * 8 + ccol;
            float v0 = acc[mt][nt][0], v1 = acc[mt][nt][1];
            float v2 = acc[mt][nt][2], v3 = acc[mt][nt][3];
            if (BIASM == 1) {
                const float b0 = bias[cg], b1 = bias[cg + 1];
                v0 += b0; v1 += b1; v2 += b0; v3 += b1;
            }
            if (BIASM == 2) {
                const float b0 = bias[r0g], b1 = bias[r0g + 8];
                v0 += b0; v1 += b0; v2 += b1; v3 += b1;
            }
            if (OUTM == 0) {
                *reinterpret_cast<float2*>(&Cf[zC + r0g * ldc + cg])       = make_float2(v0, v1);
                *reinterpret_cast<float2*>(&Cf[zC + (r0g + 8) * ldc + cg]) = make_float2(v2, v3);
            } else {
                *reinterpret_cast<uint32_t*>(&Ch[zC + r0g * ldc + cg])       = round2h(v0, v1);
                *reinterpret_cast<uint32_t*>(&Ch[zC + (r0g + 8) * ldc + cg]) = round2h(v2, v3);
            }
        }
    }
}

// ---------------------------------------------------------------------------
// Elementwise fp32 -> fp16
// ---------------------------------------------------------------------------
__global__ void round_kernel(const float* __restrict__ src, h16* __restrict__ h, size_t n4)
{
    size_t i = (size_t)blockIdx.x * blockDim.x + threadIdx.x;
    if (i >= n4) return;
    float4 v = reinterpret_cast<const float4*>(src)[i];
    reinterpret_cast<uint2*>(h)[i] = make_uint2(round2h(v.x, v.y), round2h(v.z, v.w));
}

// cached_k [B,KC,D] -> fp16 into front rows of g_kh (row stride KTP per batch)
__global__ void cachek_kernel(const float* __restrict__ ck)
{
    const size_t per = (size_t)KC * DIMN / 4;
    size_t i = (size_t)blockIdx.x * blockDim.x + threadIdx.x;
    if (i >= BATCH * per) return;
    size_t b = i / per, r = i - b * per;
    float4 v = reinterpret_cast<const float4*>(ck)[i];
    size_t dst = b * ((size_t)KTP * DIMN / 4) + r;
    reinterpret_cast<uint2*>(g_kh)[dst] = make_uint2(round2h(v.x, v.y), round2h(v.z, v.w));
}

// cached_v [B,KC,D] -> transposed into g_vh [B,D,KT] cols [0,KC)
__global__ void cachev_kernel(const float* __restrict__ cv)
{
    __shared__ float t[32][33];
    const int b = blockIdx.z;
    const int r0 = blockIdx.x * 32;   // kc
    const int c0 = blockIdx.y * 32;   // d
    const int tx = threadIdx.x, ty0 = threadIdx.y;
#pragma unroll
    for (int s = 0; s < 4; s++) {
        int ty = ty0 + s * 8;
        t[ty][tx] = cv[((size_t)b * KC + r0 + ty) * DIMN + c0 + tx];
    }
    __syncthreads();
#pragma unroll
    for (int s = 0; s < 4; s++) {
        int ty = ty0 + s * 8;
        size_t o = ((size_t)b * DIMN + c0 + ty) * KT + r0 + tx;
        g_vh[o] = __float2half_rn(t[tx][ty]);
    }
}

// ---------------------------------------------------------------------------
// Masked softmax: row q sees [0, KC+q+1); emits fp16 weights (0 beyond).
// ---------------------------------------------------------------------------
__global__ void softmax_kernel(const float* __restrict__ S, h16* __restrict__ Wh,
                               float scale)
{
    __shared__ float sbuf[KT];
    __shared__ float red[256];
    const int q = blockIdx.x, b = blockIdx.y;
    const float* row = S + ((size_t)b * LQ + q) * KTP;
    h16* wh = Wh + ((size_t)b * LQ + q) * KT;
    const int valid = KC + q + 1;
    const int tid = threadIdx.x;

    float m = -1e30f;
    for (int c = tid; c < valid; c += 256) m = fmaxf(m, row[c] * scale);
    red[tid] = m; __syncthreads();
    for (int s = 128; s > 0; s >>= 1) { if (tid < s) red[tid] = fmaxf(red[tid], red[tid + s]); __syncthreads(); }
    m = red[0]; __syncthreads();

    float sum = 0.f;
    for (int c = tid; c < valid; c += 256) {
        float e = __expf(row[c] * scale - m);
        sbuf[c] = e;
        sum += e;
    }
    red[tid] = sum; __syncthreads();
    for (int s = 128; s > 0; s >>= 1) { if (tid < s) red[tid] += red[tid + s]; __syncthreads(); }
    const float inv = 1.f / red[0];
    __syncthreads();

    for (int c = tid; c < KT; c += 256)
        wh[c] = __float2half_rn((c < valid) ? sbuf[c] * inv : 0.f);
}

// ---------------------------------------------------------------------------
// kernel_launch — graph captured with event-forked streams:
//   s0: chunk/Wq rounds -> Q proj -> (wait K) S -> softmax -> (wait V) AV ->
//       (wait Wo) O
//   s1: Wk round + cachek + (wait chunk) K proj
//   s2: Wv round + cachev + (wait chunk) V^T proj + Wo round
// ---------------------------------------------------------------------------
extern "C" void kernel_launch(void* const* d_in, const int* in_sizes, int n_in,
                              void* d_out, int out_size)
{
    const float* chunk    = (const float*)d_in[0];
    const float* cached_k = (const float*)d_in[1];
    const float* cached_v = (const float*)d_in[2];
    int wi = 3;
    while (wi < n_in && in_sizes[wi] != DIMN * DIMN) wi++;
    const float* Wq = (const float*)d_in[wi + 0];
    const float* bq = (const float*)d_in[wi + 1];
    const float* Wk = (const float*)d_in[wi + 2];
    const float* bk = (const float*)d_in[wi + 3];
    const float* Wv = (const float*)d_in[wi + 4];
    const float* bv = (const float*)d_in[wi + 5];
    const float* Wo = (const float*)d_in[wi + 6];
    const float* bo = (const float*)d_in[wi + 7];
    float* out = (float*)d_out;

    h16 *ch, *wqh, *wkh, *wvh, *woh, *qh, *kh, *vh, *phh, *ahh;
    float* s;
    cudaGetSymbolAddress((void**)&ch, g_ch);
    cudaGetSymbolAddress((void**)&wqh, g_wqh);
    cudaGetSymbolAddress((void**)&wkh, g_wkh);
    cudaGetSymbolAddress((void**)&wvh, g_wvh);
    cudaGetSymbolAddress((void**)&woh, g_woh);
    cudaGetSymbolAddress((void**)&qh, g_qh);
    cudaGetSymbolAddress((void**)&kh, g_kh);
    cudaGetSymbolAddress((void**)&vh, g_vh);
    cudaGetSymbolAddress((void**)&s, g_s);
    cudaGetSymbolAddress((void**)&phh, g_ph);
    cudaGetSymbolAddress((void**)&ahh, g_ah);

    cudaFuncSetAttribute(gemm_mma<1,1,0>, cudaFuncAttributeMaxDynamicSharedMemorySize, SMEM_MMA);
    cudaFuncSetAttribute(gemm_mma<1,2,0>, cudaFuncAttributeMaxDynamicSharedMemorySize, SMEM_MMA);
    cudaFuncSetAttribute(gemm_mma<0,0,1>, cudaFuncAttributeMaxDynamicSharedMemorySize, SMEM_MMA);
    cudaFuncSetAttribute(gemm_mma<1,0,2>, cudaFuncAttributeMaxDynamicSharedMemorySize, SMEM_MMA);
    cudaFuncSetAttribute(gemm_mma<0,1,0>, cudaFuncAttributeMaxDynamicSharedMemorySize, SMEM_MMA);

    // one-time host-side handles (no device memory involved)
    static cudaStream_t s1 = nullptr, s2 = nullptr;
    static cudaEvent_t e0 = nullptr, eK = nullptr, eV = nullptr, eW = nullptr, eF = nullptr;
    if (s1 == nullptr) {
        cudaStreamCreateWithFlags(&s1, cudaStreamNonBlocking);
        cudaStreamCreateWithFlags(&s2, cudaStreamNonBlocking);
        cudaEventCreateWithFlags(&e0, cudaEventDisableTiming);
        cudaEventCreateWithFlags(&eK, cudaEventDisableTiming);
        cudaEventCreateWithFlags(&eV, cudaEventDisableTiming);
        cudaEventCreateWithFlags(&eW, cudaEventDisableTiming);
        cudaEventCreateWithFlags(&eF, cudaEventDisableTiming);
    }

    const float scale = (float)(1.0 / sqrt((double)DIMN));
    const size_t w4 = (size_t)DIMN * DIMN / 4;
    const unsigned wg = (unsigned)((w4 + 255) / 256);

    // --- fork immediately: weight rounds + cache conversions don't need chunk
    cudaEventRecord(eF, 0);
    cudaStreamWaitEvent(s1, eF, 0);
    cudaStreamWaitEvent(s2, eF, 0);

    // s0: chunk + Wq rounds
    {
        size_t n4 = (size_t)BATCH * LQ * DIMN / 4;
        round_kernel<<<(unsigned)((n4 + 255) / 256), 256>>>(chunk, ch, n4);
        round_kernel<<<wg, 256>>>(Wq, wqh, w4);
    }
    cudaEventRecord(e0, 0);              // chunk ready

    // s1: Wk round + cached K, then (after chunk) K projection
    {
        round_kernel<<<wg, 256, 0, s1>>>(Wk, wkh, w4);
        size_t ck4 = (size_t)BATCH * KC * DIMN / 4;
        cachek_kernel<<<(unsigned)((ck4 + 255) / 256), 256, 0, s1>>>(cached_k);
        cudaStreamWaitEvent(s1, e0, 0);
        gemm_mma<1,1,0><<<dim3(DIMN / BNT, LQ / BMT, BATCH), 256, SMEM_MMA, s1>>>(
            ch, wkh, bk, nullptr, kh + (size_t)KC * DIMN,
            DIMN, DIMN, DIMN, DIMN,
            (long long)LQ * DIMN, 0, (long long)KTP * DIMN);
        cudaEventRecord(eK, s1);
    }

    // s2: Wv round + cached V, then (after chunk) V^T projection, then Wo round
    {
        round_kernel<<<wg, 256, 0, s2>>>(Wv, wvh, w4);
        cachev_kernel<<<dim3(KC / 32, DIMN / 32, BATCH), dim3(32, 8), 0, s2>>>(cached_v);
        cudaStreamWaitEvent(s2, e0, 0);
        gemm_mma<1,2,0><<<dim3(LQ / BNT, DIMN / BMT, BATCH), 256, SMEM_MMA, s2>>>(
            wvh, ch, bv, nullptr, vh + KC,
            DIMN, DIMN, DIMN, KT,
            0, (long long)LQ * DIMN, (long long)DIMN * KT);
        cudaEventRecord(eV, s2);
        round_kernel<<<wg, 256, 0, s2>>>(Wo, woh, w4);
        cudaEventRecord(eW, s2);
    }

    // s0: Q projection
    gemm_mma<1,1,0><<<dim3(DIMN / BNT, (BATCH * LQ) / BMT, 1), 256, SMEM_MMA>>>(
        ch, wqh, bq, nullptr, qh,
        DIMN, DIMN, DIMN, DIMN, 0, 0, 0);

    // join K, then S = Q @ K^T (masked + pad tiles skipped)
    cudaStreamWaitEvent(0, eK, 0);
    gemm_mma<0,0,1><<<dim3(KTP / BNT, LQ / BMT, BATCH), 256, SMEM_MMA>>>(
        qh, kh, nullptr, s, nullptr,
        DIMN, DIMN, DIMN, KTP,
        (long long)LQ * DIMN, (long long)KTP * DIMN, (long long)LQ * KTP);

    // masked softmax -> fp16 weights
    softmax_kernel<<<dim3(LQ, BATCH), 256>>>(s, phh, scale);

    // join V, then attended = P @ V (K loop clamped, heavy rows first)
    cudaStreamWaitEvent(0, eV, 0);
    gemm_mma<1,0,2><<<dim3(DIMN / BNT, LQ / BMT, BATCH), 256, SMEM_MMA>>>(
        phh, vh, nullptr, nullptr, ahh,
        KT, KT, KT, DIMN,
        (long long)LQ * KT, (long long)DIMN * KT, (long long)LQ * DIMN);

    // join Wo round, then output projection -> fp32 out
    cudaStreamWaitEvent(0, eW, 0);
    gemm_mma<0,1,0><<<dim3(DIMN / BNT, (BATCH * LQ) / BMT, 1), 256, SMEM_MMA>>>(
        ahh, woh, bo, out, nullptr,
        DIMN, DIMN, DIMN, DIMN, 0, 0, 0);
}

// round 15
// speedup vs baseline: 1.5385x; 1.5385x over previous
#include <cuda_runtime.h>
#include <cuda_fp16.h>
#include <math.h>
#include <stdint.h>

#define DIMN 2048
#define BATCH 4
#define LQ    4096
#define KC    576
#define KT    4672          // KC + LQ
#define KTP   4864          // padded N for the S GEMM (38*128)

typedef __half h16;

// ---------------------------------------------------------------------------
// Scratch (__device__ globals — zero-initialized; K rows [KT,KTP) stay 0)
// Fully single-pass fp16 scheme (calibrated error ~6e-4 < 1e-3).
// ---------------------------------------------------------------------------
__device__ h16 g_ch [(size_t)BATCH*LQ*DIMN];   // chunk (fp16)
__device__ h16 g_wqh[(size_t)DIMN*DIMN];
__device__ h16 g_wkh[(size_t)DIMN*DIMN];
__device__ h16 g_wvh[(size_t)DIMN*DIMN];
__device__ h16 g_woh[(size_t)DIMN*DIMN];
__device__ h16 g_qh [(size_t)BATCH*LQ*DIMN];
__device__ h16 g_kh [(size_t)BATCH*KTP*DIMN];
__device__ h16 g_vh [(size_t)BATCH*DIMN*KT];   // V^T [b][d][kt]
__device__ float g_s [(size_t)BATCH*LQ*KTP];
__device__ h16 g_ph [(size_t)BATCH*LQ*KT];
__device__ h16 g_ah [(size_t)BATCH*LQ*DIMN];

// ---------------------------------------------------------------------------
// helpers
// ---------------------------------------------------------------------------
__device__ __forceinline__ uint32_t s2u(const void* p) {
    uint32_t a;
    asm("{ .reg .u64 t; cvta.to.shared.u64 t, %1; cvt.u32.u64 %0, t; }" : "=r"(a) : "l"(p));
    return a;
}
__device__ __forceinline__ void cpa16(uint32_t d, const void* s) {
    asm volatile("cp.async.cg.shared.global [%0], [%1], 16;" :: "r"(d), "l"(s));
}
#define CP_COMMIT() asm volatile("cp.async.commit_group;" ::: "memory")
#define CP_WAIT1()  asm volatile("cp.async.wait_group 1;" ::: "memory")
#define CP_WAIT0()  asm volatile("cp.async.wait_group 0;" ::: "memory")

#define LDSM4(r, a) \
    asm volatile("ldmatrix.sync.aligned.m8n8.x4.shared.b16 {%0,%1,%2,%3}, [%4];" \
                 : "=r"((r)[0]), "=r"((r)[1]), "=r"((r)[2]), "=r"((r)[3]) : "r"(a))

__device__ __forceinline__ void mma16816(float* d, const uint32_t* a,
                                         uint32_t b0, uint32_t b1) {
    asm volatile(
        "mma.sync.aligned.m16n8k16.row.col.f32.f16.f16.f32 "
        "{%0,%1,%2,%3}, {%4,%5,%6,%7}, {%8,%9}, {%0,%1,%2,%3};"
        : "+f"(d[0]), "+f"(d[1]), "+f"(d[2]), "+f"(d[3])
        : "r"(a[0]), "r"(a[1]), "r"(a[2]), "r"(a[3]), "r"(b0), "r"(b1));
}

__device__ __forceinline__ uint32_t round2h(float x0, float x1) {
    __half2 hp = __floats2half2_rn(x0, x1);
    return *reinterpret_cast<uint32_t*>(&hp);
}

// ---------------------------------------------------------------------------
// fp16 single-pass mma.sync GEMM: C tile 128x128, BK=32, 3-stage cp.async
// pipeline, ONE __syncthreads per k-chunk. C = A·B^T, fp32 accum.
// A[M,K], B[N,K] row-major (NT).
// OUTM: 0 fp32 out, 1 fp16 out.
// BIASM: 0 none, 1 bias[col], 2 bias[row]
// TRI:  0 none, 1 = skip block if col0 >= KC+row0+BMT or col0 >= KT (S GEMM),
//       2 = clamp K loop to KC+row0+BMT (AV GEMM; heavy rows scheduled first)
// ---------------------------------------------------------------------------
#define BMT 128
#define BNT 128
#define BKT 32
#define APAD 40                          // fp16 row stride (32+8) -> 80B
#define TILE_B (128 * APAD * 2)          // 10240 bytes per tile
#define STAGE_B (2 * TILE_B)             // A|B = 20480
#define SMEM_MMA (3 * STAGE_B)           // 61440 bytes (3 stages) -> 2 CTAs/SM

template<int OUTM, int BIASM, int TRI>
__global__ __launch_bounds__(256, 2)
void gemm_mma(const h16* __restrict__ Ah,
              const h16* __restrict__ Bh,
              const float* __restrict__ bias,
              float* __restrict__ Cf, h16* __restrict__ Ch,
              int K, int lda, int ldb, int ldc,
              long long sA, long long sB, long long sC)
{
    // TRI==2: reverse row order so the heaviest (longest-K) CTAs start first
    const int row0 = (TRI == 2 ? (int)(gridDim.y - 1 - blockIdx.y) : (int)blockIdx.y) * BMT;
    const int col0 = blockIdx.x * BNT;
    if (TRI == 1 && (col0 >= KC + row0 + BMT || col0 >= KT)) return; // masked / pad tile

    extern __shared__ h16 sm[];
    const uint32_t smb = s2u(sm);
    const int tid  = threadIdx.x;
    const int lane = tid & 31, warp = tid >> 5;
    const int wm = warp & 1, wn = warp >> 1;    // warp grid 2 (M) x 4 (N)
    const size_t zA = (size_t)blockIdx.z * sA;
    const size_t zB = (size_t)blockIdx.z * sB;
    const size_t zC = (size_t)blockIdx.z * sC;

    int kchunks = K / BKT;
    if (TRI == 2) {
        int lim = (KC + row0 + BMT) / BKT;      // multiple of 32 by construction
        if (lim < kchunks) kchunks = lim;
    }

    // cp.async mapping: rows (tid>>2) and (tid>>2)+64, 16B chunk (tid&3)*8
    const int lrow = tid >> 2;
    const int lcol = (tid & 3) * 8;
    const uint32_t o1 = (lrow * APAD + lcol) * 2;
    const uint32_t o2 = ((lrow + 64) * APAD + lcol) * 2;

    auto issue = [&](int kc, int st) {
        const size_t ao = zA + (size_t)(row0 + lrow) * lda + (size_t)kc * BKT + lcol;
        const size_t bo = zB + (size_t)(col0 + lrow) * ldb + (size_t)kc * BKT + lcol;
        const uint32_t base = smb + st * STAGE_B;
        cpa16(base + o1,          Ah + ao);
        cpa16(base + o2,          Ah + ao + (size_t)64 * lda);
        cpa16(base + TILE_B + o1, Bh + bo);
        cpa16(base + TILE_B + o2, Bh + bo + (size_t)64 * ldb);
    };

    float acc[4][4][4];
#pragma unroll
    for (int i = 0; i < 4; i++)
#pragma unroll
        for (int j = 0; j < 4; j++)
#pragma unroll
            for (int e = 0; e < 4; e++) acc[i][j][e] = 0.f;

    // ldmatrix per-thread address components
    const int am = wm * 64 + (lane & 15);
    const int ak = (lane >> 4) * 8;
    const int bn = wn * 32 + (lane & 15);

    // prologue: fill 2 of the 3 stages
    issue(0, 0); CP_COMMIT();
    if (kchunks > 1) { issue(1, 1); CP_COMMIT(); }

    int st = 0;
    for (int kc = 0; kc < kchunks; ++kc) {
        if (kc + 1 < kchunks) CP_WAIT1(); else CP_WAIT0();
        __syncthreads();   // also covers the WAR hazard for stage (kc+2)%3

        if (kc + 2 < kchunks) {
            int st2 = st + 2; if (st2 >= 3) st2 -= 3;
            issue(kc + 2, st2);
            CP_COMMIT();
        }

        const uint32_t ah_ = smb + st * STAGE_B;
        const uint32_t bh_ = ah_ + TILE_B;
#pragma unroll
        for (int ks = 0; ks < 2; ks++) {
            uint32_t af[4][4], bh[2][4];
#pragma unroll
            for (int mt = 0; mt < 4; mt++)
                LDSM4(af[mt], ah_ + (((am + mt * 16) * APAD) + ks * 16 + ak) * 2);
#pragma unroll
            for (int pr = 0; pr < 2; pr++)
                LDSM4(bh[pr], bh_ + (((bn + pr * 16) * APAD) + ks * 16 + ak) * 2);
#pragma unroll
            for (int mt = 0; mt < 4; mt++)
#pragma unroll
                for (int nt = 0; nt < 4; nt++)
                    mma16816(acc[mt][nt], af[mt],
                             bh[nt >> 1][nt & 1], bh[nt >> 1][(nt & 1) + 2]);
        }
        if (++st == 3) st = 0;
    }

    // epilogue
    const int crow = lane >> 2;
    const int ccol = (lane & 3) * 2;
#pragma unroll
    for (int mt = 0; mt < 4; mt++) {
        const size_t r0g = (size_t)row0 + wm * 64 + mt * 16 + crow;
#pragma unroll
        for (int nt = 0; nt < 4; nt++) {
            const int cg = col0 + wn * 32 + nt * 8 + ccol;
            float v0 = acc[mt][nt][0], v1 = acc[mt][nt][1];
            float v2 = acc[mt][nt][2], v3 = acc[mt][nt][3];
            if (BIASM == 1) {
                const float b0 = bias[cg], b1 = bias[cg + 1];
                v0 += b0; v1 += b1; v2 += b0; v3 += b1;
            }
            if (BIASM == 2) {
                const float b0 = bias[r0g], b1 = bias[r0g + 8];
                v0 += b0; v1 += b0; v2 += b1; v3 += b1;
            }
            if (OUTM == 0) {
                *reinterpret_cast<float2*>(&Cf[zC + r0g * ldc + cg])       = make_float2(v0, v1);
                *reinterpret_cast<float2*>(&Cf[zC + (r0g + 8) * ldc + cg]) = make_float2(v2, v3);
            } else {
                *reinterpret_cast<uint32_t*>(&Ch[zC + r0g * ldc + cg])       = round2h(v0, v1);
                *reinterpret_cast<uint32_t*>(&Ch[zC + (r0g + 8) * ldc + cg]) = round2h(v2, v3);
            }
        }
    }
}

// ---------------------------------------------------------------------------
// Elementwise fp32 -> fp16
// ---------------------------------------------------------------------------
__global__ void round_kernel(const float* __restrict__ src, h16* __restrict__ h, size_t n4)
{
    size_t i = (size_t)blockIdx.x * blockDim.x + threadIdx.x;
    if (i >= n4) return;
    float4 v = reinterpret_cast<const float4*>(src)[i];
    reinterpret_cast<uint2*>(h)[i] = make_uint2(round2h(v.x, v.y), round2h(v.z, v.w));
}

// cached_k [B,KC,D] -> fp16 into front rows of g_kh (row stride KTP per batch)
__global__ void cachek_kernel(const float* __restrict__ ck)
{
    const size_t per = (size_t)KC * DIMN / 4;
    size_t i = (size_t)blockIdx.x * blockDim.x + threadIdx.x;
    if (i >= BATCH * per) return;
    size_t b = i / per, r = i - b * per;
    float4 v = reinterpret_cast<const float4*>(ck)[i];
    size_t dst = b * ((size_t)KTP * DIMN / 4) + r;
    reinterpret_cast<uint2*>(g_kh)[dst] = make_uint2(round2h(v.x, v.y), round2h(v.z, v.w));
}

// cached_v [B,KC,D] -> transposed into g_vh [B,D,KT] cols [0,KC)
__global__ void cachev_kernel(const float* __restrict__ cv)
{
    __shared__ float t[32][33];
    const int b = blockIdx.z;
    const int r0 = blockIdx.x * 32;   // kc
    const int c0 = blockIdx.y * 32;   // d
    const int tx = threadIdx.x, ty0 = threadIdx.y;
#pragma unroll
    for (int s = 0; s < 4; s++) {
        int ty = ty0 + s * 8;
        t[ty][tx] = cv[((size_t)b * KC + r0 + ty) * DIMN + c0 + tx];
    }
    __syncthreads();
#pragma unroll
    for (int s = 0; s < 4; s++) {
        int ty = ty0 + s * 8;
        size_t o = ((size_t)b * DIMN + c0 + ty) * KT + r0 + tx;
        g_vh[o] = __float2half_rn(t[tx][ty]);
    }
}

// ---------------------------------------------------------------------------
// Masked softmax: row q sees [0, KC+q+1); emits fp16 weights (0 beyond).
// 512 threads per row-block.
// ---------------------------------------------------------------------------
__global__ void softmax_kernel(const float* __restrict__ S, h16* __restrict__ Wh,
                               float scale)
{
    __shared__ float sbuf[KT];
    __shared__ float red[512];
    const int q = blockIdx.x, b = blockIdx.y;
    const float* row = S + ((size_t)b * LQ + q) * KTP;
    h16* wh = Wh + ((size_t)b * LQ + q) * KT;
    const int valid = KC + q + 1;
    const int tid = threadIdx.x;

    float m = -1e30f;
    for (int c = tid; c < valid; c += 512) m = fmaxf(m, row[c] * scale);
    red[tid] = m; __syncthreads();
    for (int s = 256; s > 0; s >>= 1) { if (tid < s) red[tid] = fmaxf(red[tid], red[tid + s]); __syncthreads(); }
    m = red[0]; __syncthreads();

    float sum = 0.f;
    for (int c = tid; c < valid; c += 512) {
        float e = __expf(row[c] * scale - m);
        sbuf[c] = e;
        sum += e;
    }
    red[tid] = sum; __syncthreads();
    for (int s = 256; s > 0; s >>= 1) { if (tid < s) red[tid] += red[tid + s]; __syncthreads(); }
    const float inv = 1.f / red[0];
    __syncthreads();

    for (int c = tid; c < KT; c += 512)
        wh[c] = __float2half_rn((c < valid) ? sbuf[c] * inv : 0.f);
}

// ---------------------------------------------------------------------------
// kernel_launch — R12 graph structure (known-good):
//   s0(default): ALL conversions -> Q proj -> (wait K) S -> softmax ->
//                (wait V) AV -> O
//   s1: cachek + K proj        s2: cachev + V^T proj (overlaps S/softmax)
// ---------------------------------------------------------------------------
extern "C" void kernel_launch(void* const* d_in, const int* in_sizes, int n_in,
                              void* d_out, int out_size)
{
    const float* chunk    = (const float*)d_in[0];
    const float* cached_k = (const float*)d_in[1];
    const float* cached_v = (const float*)d_in[2];
    int wi = 3;
    while (wi < n_in && in_sizes[wi] != DIMN * DIMN) wi++;
    const float* Wq = (const float*)d_in[wi + 0];
    const float* bq = (const float*)d_in[wi + 1];
    const float* Wk = (const float*)d_in[wi + 2];
    const float* bk = (const float*)d_in[wi + 3];
    const float* Wv = (const float*)d_in[wi + 4];
    const float* bv = (const float*)d_in[wi + 5];
    const float* Wo = (const float*)d_in[wi + 6];
    const float* bo = (const float*)d_in[wi + 7];
    float* out = (float*)d_out;

    h16 *ch, *wqh, *wkh, *wvh, *woh, *qh, *kh, *vh, *phh, *ahh;
    float* s;
    cudaGetSymbolAddress((void**)&ch, g_ch);
    cudaGetSymbolAddress((void**)&wqh, g_wqh);
    cudaGetSymbolAddress((void**)&wkh, g_wkh);
    cudaGetSymbolAddress((void**)&wvh, g_wvh);
    cudaGetSymbolAddress((void**)&woh, g_woh);
    cudaGetSymbolAddress((void**)&qh, g_qh);
    cudaGetSymbolAddress((void**)&kh, g_kh);
    cudaGetSymbolAddress((void**)&vh, g_vh);
    cudaGetSymbolAddress((void**)&s, g_s);
    cudaGetSymbolAddress((void**)&phh, g_ph);
    cudaGetSymbolAddress((void**)&ahh, g_ah);

    cudaFuncSetAttribute(gemm_mma<1,1,0>, cudaFuncAttributeMaxDynamicSharedMemorySize, SMEM_MMA);
    cudaFuncSetAttribute(gemm_mma<1,2,0>, cudaFuncAttributeMaxDynamicSharedMemorySize, SMEM_MMA);
    cudaFuncSetAttribute(gemm_mma<0,0,1>, cudaFuncAttributeMaxDynamicSharedMemorySize, SMEM_MMA);
    cudaFuncSetAttribute(gemm_mma<1,0,2>, cudaFuncAttributeMaxDynamicSharedMemorySize, SMEM_MMA);
    cudaFuncSetAttribute(gemm_mma<0,1,0>, cudaFuncAttributeMaxDynamicSharedMemorySize, SMEM_MMA);

    // one-time host-side handles (no device memory involved)
    static cudaStream_t s1 = nullptr, s2 = nullptr;
    static cudaEvent_t e0 = nullptr, eK = nullptr, eV = nullptr;
    if (s1 == nullptr) {
        cudaStreamCreateWithFlags(&s1, cudaStreamNonBlocking);
        cudaStreamCreateWithFlags(&s2, cudaStreamNonBlocking);
        cudaEventCreateWithFlags(&e0, cudaEventDisableTiming);
        cudaEventCreateWithFlags(&eK, cudaEventDisableTiming);
        cudaEventCreateWithFlags(&eV, cudaEventDisableTiming);
    }

    const float scale = (float)(1.0 / sqrt((double)DIMN));

    // --- conversions on the capture (default) stream
    {
        size_t n4 = (size_t)BATCH * LQ * DIMN / 4;
        round_kernel<<<(unsigned)((n4 + 255) / 256), 256>>>(chunk, ch, n4);
        size_t w4 = (size_t)DIMN * DIMN / 4;
        unsigned wg = (unsigned)((w4 + 255) / 256);
        round_kernel<<<wg, 256>>>(Wq, wqh, w4);
        round_kernel<<<wg, 256>>>(Wk, wkh, w4);
        round_kernel<<<wg, 256>>>(Wv, wvh, w4);
        round_kernel<<<wg, 256>>>(Wo, woh, w4);
    }
    cudaEventRecord(e0, 0);
    cudaStreamWaitEvent(s1, e0, 0);
    cudaStreamWaitEvent(s2, e0, 0);

    // --- s1: cached K + K projection
    {
        size_t ck4 = (size_t)BATCH * KC * DIMN / 4;
        cachek_kernel<<<(unsigned)((ck4 + 255) / 256), 256, 0, s1>>>(cached_k);
        gemm_mma<1,1,0><<<dim3(DIMN / BNT, LQ / BMT, BATCH), 256, SMEM_MMA, s1>>>(
            ch, wkh, bk, nullptr, kh + (size_t)KC * DIMN,
            DIMN, DIMN, DIMN, DIMN,
            (long long)LQ * DIMN, 0, (long long)KTP * DIMN);
        cudaEventRecord(eK, s1);
    }

    // --- s2: cached V + V^T projection
    {
        cachev_kernel<<<dim3(KC / 32, DIMN / 32, BATCH), dim3(32, 8), 0, s2>>>(cached_v);
        gemm_mma<1,2,0><<<dim3(LQ / BNT, DIMN / BMT, BATCH), 256, SMEM_MMA, s2>>>(
            wvh, ch, bv, nullptr, vh + KC,
            DIMN, DIMN, DIMN, KT,
            0, (long long)LQ * DIMN, (long long)DIMN * KT);
        cudaEventRecord(eV, s2);
    }

    // --- s0: Q projection
    gemm_mma<1,1,0><<<dim3(DIMN / BNT, (BATCH * LQ) / BMT, 1), 256, SMEM_MMA>>>(
        ch, wqh, bq, nullptr, qh,
        DIMN, DIMN, DIMN, DIMN, 0, 0, 0);

    // join K, then S = Q @ K^T (masked + pad tiles skipped)
    cudaStreamWaitEvent(0, eK, 0);
    gemm_mma<0,0,1><<<dim3(KTP / BNT, LQ / BMT, BATCH), 256, SMEM_MMA>>>(
        qh, kh, nullptr, s, nullptr,
        DIMN, DIMN, DIMN, KTP,
        (long long)LQ * DIMN, (long long)KTP * DIMN, (long long)LQ * KTP);

    // masked softmax -> fp16 weights
    softmax_kernel<<<dim3(LQ, BATCH), 512>>>(s, phh, scale);

    // join V, then attended = P @ V (K loop clamped, heavy rows first)
    cudaStreamWaitEvent(0, eV, 0);
    gemm_mma<1,0,2><<<dim3(DIMN / BNT, LQ / BMT, BATCH), 256, SMEM_MMA>>>(
        phh, vh, nullptr, nullptr, ahh,
        KT, KT, KT, DIMN,
        (long long)LQ * KT, (long long)DIMN * KT, (long long)LQ * DIMN);

    // output projection: attended @ Wo^T + bo -> fp32 out
    gemm_mma<0,1,0><<<dim3(DIMN / BNT, (BATCH * LQ) / BMT, 1), 256, SMEM_MMA>>>(
        ahh, woh, bo, out, nullptr,
        DIMN, DIMN, DIMN, DIMN, 0, 0, 0);
}

// round 16
// speedup vs baseline: 1.5636x; 1.0163x over previous
#include <cuda_runtime.h>
#include <cuda_fp16.h>
#include <math.h>
#include <stdint.h>

#define DIMN 2048
#define BATCH 4
#define LQ    4096
#define KC    576
#define KT    4672          // KC + LQ
#define KTP   4864          // padded N for the S GEMM (38*128)

typedef __half h16;

// ---------------------------------------------------------------------------
// Scratch (__device__ globals — zero-initialized; K rows [KT,KTP) stay 0)
// Fully single-pass fp16 scheme (calibrated error ~6e-4 < 1e-3).
// ---------------------------------------------------------------------------
__device__ h16 g_ch [(size_t)BATCH*LQ*DIMN];   // chunk (fp16)
__device__ h16 g_wqh[(size_t)DIMN*DIMN];
__device__ h16 g_wkh[(size_t)DIMN*DIMN];
__device__ h16 g_wvh[(size_t)DIMN*DIMN];
__device__ h16 g_woh[(size_t)DIMN*DIMN];
__device__ h16 g_qh [(size_t)BATCH*LQ*DIMN];
__device__ h16 g_kh [(size_t)BATCH*KTP*DIMN];
__device__ h16 g_vh [(size_t)BATCH*DIMN*KT];   // V^T [b][d][kt]
__device__ float g_s [(size_t)BATCH*LQ*KTP];
__device__ h16 g_ph [(size_t)BATCH*LQ*KT];
__device__ h16 g_ah [(size_t)BATCH*LQ*DIMN];

// ---------------------------------------------------------------------------
// helpers
// ---------------------------------------------------------------------------
__device__ __forceinline__ uint32_t s2u(const void* p) {
    uint32_t a;
    asm("{ .reg .u64 t; cvta.to.shared.u64 t, %1; cvt.u32.u64 %0, t; }" : "=r"(a) : "l"(p));
    return a;
}
__device__ __forceinline__ void cpa16(uint32_t d, const void* s) {
    asm volatile("cp.async.cg.shared.global [%0], [%1], 16;" :: "r"(d), "l"(s));
}
#define CP_COMMIT() asm volatile("cp.async.commit_group;" ::: "memory")
#define CP_WAIT1()  asm volatile("cp.async.wait_group 1;" ::: "memory")
#define CP_WAIT0()  asm volatile("cp.async.wait_group 0;" ::: "memory")

#define LDSM4(r, a) \
    asm volatile("ldmatrix.sync.aligned.m8n8.x4.shared.b16 {%0,%1,%2,%3}, [%4];" \
                 : "=r"((r)[0]), "=r"((r)[1]), "=r"((r)[2]), "=r"((r)[3]) : "r"(a))

__device__ __forceinline__ void mma16816(float* d, const uint32_t* a,
                                         uint32_t b0, uint32_t b1) {
    asm volatile(
        "mma.sync.aligned.m16n8k16.row.col.f32.f16.f16.f32 "
        "{%0,%1,%2,%3}, {%4,%5,%6,%7}, {%8,%9}, {%0,%1,%2,%3};"
        : "+f"(d[0]), "+f"(d[1]), "+f"(d[2]), "+f"(d[3])
        : "r"(a[0]), "r"(a[1]), "r"(a[2]), "r"(a[3]), "r"(b0), "r"(b1));
}

__device__ __forceinline__ uint32_t round2h(float x0, float x1) {
    __half2 hp = __floats2half2_rn(x0, x1);
    return *reinterpret_cast<uint32_t*>(&hp);
}

// ---------------------------------------------------------------------------
// fp16 single-pass mma.sync GEMM: C tile 128x128, BK=32, 3-stage cp.async
// pipeline, ONE __syncthreads per k-chunk. C = A·B^T, fp32 accum.
// A[M,K], B[N,K] row-major (NT).
// OUTM: 0 fp32 out, 1 fp16 out.
// BIASM: 0 none, 1 bias[col], 2 bias[row]
// TRI:  0 none, 1 = skip block if col0 >= KC+row0+BMT or col0 >= KT (S GEMM),
//       2 = clamp K loop to KC+row0+BMT (AV GEMM; heavy rows scheduled first)
// ---------------------------------------------------------------------------
#define BMT 128
#define BNT 128
#define BKT 32
#define APAD 40                          // fp16 row stride (32+8) -> 80B
#define TILE_B (128 * APAD * 2)          // 10240 bytes per tile
#define STAGE_B (2 * TILE_B)             // A|B = 20480
#define SMEM_MMA (3 * STAGE_B)           // 61440 bytes (3 stages) -> 2 CTAs/SM

template<int OUTM, int BIASM, int TRI>
__global__ __launch_bounds__(256, 2)
void gemm_mma(const h16* __restrict__ Ah,
              const h16* __restrict__ Bh,
              const float* __restrict__ bias,
              float* __restrict__ Cf, h16* __restrict__ Ch,
              int K, int lda, int ldb, int ldc,
              long long sA, long long sB, long long sC)
{
    // TRI==2: reverse row order so the heaviest (longest-K) CTAs start first
    const int row0 = (TRI == 2 ? (int)(gridDim.y - 1 - blockIdx.y) : (int)blockIdx.y) * BMT;
    const int col0 = blockIdx.x * BNT;
    if (TRI == 1 && (col0 >= KC + row0 + BMT || col0 >= KT)) return; // masked / pad tile

    extern __shared__ h16 sm[];
    const uint32_t smb = s2u(sm);
    const int tid  = threadIdx.x;
    const int lane = tid & 31, warp = tid >> 5;
    const int wm = warp & 1, wn = warp >> 1;    // warp grid 2 (M) x 4 (N)
    const size_t zA = (size_t)blockIdx.z * sA;
    const size_t zB = (size_t)blockIdx.z * sB;
    const size_t zC = (size_t)blockIdx.z * sC;

    int kchunks = K / BKT;
    if (TRI == 2) {
        int lim = (KC + row0 + BMT) / BKT;      // multiple of 32 by construction
        if (lim < kchunks) kchunks = lim;
    }

    // cp.async mapping: rows (tid>>2) and (tid>>2)+64, 16B chunk (tid&3)*8
    const int lrow = tid >> 2;
    const int lcol = (tid & 3) * 8;
    const uint32_t o1 = (lrow * APAD + lcol) * 2;
    const uint32_t o2 = ((lrow + 64) * APAD + lcol) * 2;

    auto issue = [&](int kc, int st) {
        const size_t ao = zA + (size_t)(row0 + lrow) * lda + (size_t)kc * BKT + lcol;
        const size_t bo = zB + (size_t)(col0 + lrow) * ldb + (size_t)kc * BKT + lcol;
        const uint32_t base = smb + st * STAGE_B;
        cpa16(base + o1,          Ah + ao);
        cpa16(base + o2,          Ah + ao + (size_t)64 * lda);
        cpa16(base + TILE_B + o1, Bh + bo);
        cpa16(base + TILE_B + o2, Bh + bo + (size_t)64 * ldb);
    };

    float acc[4][4][4];
#pragma unroll
    for (int i = 0; i < 4; i++)
#pragma unroll
        for (int j = 0; j < 4; j++)
#pragma unroll
            for (int e = 0; e < 4; e++) acc[i][j][e] = 0.f;

    // ldmatrix per-thread address components
    const int am = wm * 64 + (lane & 15);
    const int ak = (lane >> 4) * 8;
    const int bn = wn * 32 + (lane & 15);

    // prologue: fill 2 of the 3 stages
    issue(0, 0); CP_COMMIT();
    if (kchunks > 1) { issue(1, 1); CP_COMMIT(); }

    int st = 0;
    for (int kc = 0; kc < kchunks; ++kc) {
        if (kc + 1 < kchunks) CP_WAIT1(); else CP_WAIT0();
        __syncthreads();   // also covers the WAR hazard for stage (kc+2)%3

        if (kc + 2 < kchunks) {
            int st2 = st + 2; if (st2 >= 3) st2 -= 3;
            issue(kc + 2, st2);
            CP_COMMIT();
        }

        const uint32_t ah_ = smb + st * STAGE_B;
        const uint32_t bh_ = ah_ + TILE_B;
#pragma unroll
        for (int ks = 0; ks < 2; ks++) {
            uint32_t af[4][4], bh[2][4];
#pragma unroll
            for (int mt = 0; mt < 4; mt++)
                LDSM4(af[mt], ah_ + (((am + mt * 16) * APAD) + ks * 16 + ak) * 2);
#pragma unroll
            for (int pr = 0; pr < 2; pr++)
                LDSM4(bh[pr], bh_ + (((bn + pr * 16) * APAD) + ks * 16 + ak) * 2);
#pragma unroll
            for (int mt = 0; mt < 4; mt++)
#pragma unroll
                for (int nt = 0; nt < 4; nt++)
                    mma16816(acc[mt][nt], af[mt],
                             bh[nt >> 1][nt & 1], bh[nt >> 1][(nt & 1) + 2]);
        }
        if (++st == 3) st = 0;
    }

    // epilogue
    const int crow = lane >> 2;
    const int ccol = (lane & 3) * 2;
#pragma unroll
    for (int mt = 0; mt < 4; mt++) {
        const size_t r0g = (size_t)row0 + wm * 64 + mt * 16 + crow;
#pragma unroll
        for (int nt = 0; nt < 4; nt++) {
            const int cg = col0 + wn * 32 + nt * 8 + ccol;
            float v0 = acc[mt][nt][0], v1 = acc[mt][nt][1];
            float v2 = acc[mt][nt][2], v3 = acc[mt][nt][3];
            if (BIASM == 1) {
                const float b0 = bias[cg], b1 = bias[cg + 1];
                v0 += b0; v1 += b1; v2 += b0; v3 += b1;
            }
            if (BIASM == 2) {
                const float b0 = bias[r0g], b1 = bias[r0g + 8];
                v0 += b0; v1 += b0; v2 += b1; v3 += b1;
            }
            if (OUTM == 0) {
                *reinterpret_cast<float2*>(&Cf[zC + r0g * ldc + cg])       = make_float2(v0, v1);
                *reinterpret_cast<float2*>(&Cf[zC + (r0g + 8) * ldc + cg]) = make_float2(v2, v3);
            } else {
                *reinterpret_cast<uint32_t*>(&Ch[zC + r0g * ldc + cg])       = round2h(v0, v1);
                *reinterpret_cast<uint32_t*>(&Ch[zC + (r0g + 8) * ldc + cg]) = round2h(v2, v3);
            }
        }
    }
}

// ---------------------------------------------------------------------------
// Elementwise fp32 -> fp16 (single tensor)
// ---------------------------------------------------------------------------
__global__ void round_kernel(const float* __restrict__ src, h16* __restrict__ h, size_t n4)
{
    size_t i = (size_t)blockIdx.x * blockDim.x + threadIdx.x;
    if (i >= n4) return;
    float4 v = reinterpret_cast<const float4*>(src)[i];
    reinterpret_cast<uint2*>(h)[i] = make_uint2(round2h(v.x, v.y), round2h(v.z, v.w));
}

// Fused fp32 -> fp16 for the four weight matrices (blockIdx.y selects tensor)
__global__ void round4_kernel(const float* __restrict__ w0, const float* __restrict__ w1,
                              const float* __restrict__ w2, const float* __restrict__ w3,
                              h16* __restrict__ d0, h16* __restrict__ d1,
                              h16* __restrict__ d2, h16* __restrict__ d3,
                              size_t n4)
{
    size_t i = (size_t)blockIdx.x * blockDim.x + threadIdx.x;
    if (i >= n4) return;
    const float* src = (blockIdx.y == 0) ? w0 : (blockIdx.y == 1) ? w1
                     : (blockIdx.y == 2) ? w2 : w3;
    h16* dst = (blockIdx.y == 0) ? d0 : (blockIdx.y == 1) ? d1
             : (blockIdx.y == 2) ? d2 : d3;
    float4 v = reinterpret_cast<const float4*>(src)[i];
    reinterpret_cast<uint2*>(dst)[i] = make_uint2(round2h(v.x, v.y), round2h(v.z, v.w));
}

// cached_k [B,KC,D] -> fp16 into front rows of g_kh (row stride KTP per batch)
__global__ void cachek_kernel(const float* __restrict__ ck)
{
    const size_t per = (size_t)KC * DIMN / 4;
    size_t i = (size_t)blockIdx.x * blockDim.x + threadIdx.x;
    if (i >= BATCH * per) return;
    size_t b = i / per, r = i - b * per;
    float4 v = reinterpret_cast<const float4*>(ck)[i];
    size_t dst = b * ((size_t)KTP * DIMN / 4) + r;
    reinterpret_cast<uint2*>(g_kh)[dst] = make_uint2(round2h(v.x, v.y), round2h(v.z, v.w));
}

// cached_v [B,KC,D] -> transposed into g_vh [B,D,KT] cols [0,KC)
__global__ void cachev_kernel(const float* __restrict__ cv)
{
    __shared__ float t[32][33];
    const int b = blockIdx.z;
    const int r0 = blockIdx.x * 32;   // kc
    const int c0 = blockIdx.y * 32;   // d
    const int tx = threadIdx.x, ty0 = threadIdx.y;
#pragma unroll
    for (int s = 0; s < 4; s++) {
        int ty = ty0 + s * 8;
        t[ty][tx] = cv[((size_t)b * KC + r0 + ty) * DIMN + c0 + tx];
    }
    __syncthreads();
#pragma unroll
    for (int s = 0; s < 4; s++) {
        int ty = ty0 + s * 8;
        size_t o = ((size_t)b * DIMN + c0 + ty) * KT + r0 + tx;
        g_vh[o] = __float2half_rn(t[tx][ty]);
    }
}

// ---------------------------------------------------------------------------
// Masked softmax: row q sees [0, KC+q+1); emits fp16 weights (0 beyond).
// ---------------------------------------------------------------------------
__global__ void softmax_kernel(const float* __restrict__ S, h16* __restrict__ Wh,
                               float scale)
{
    __shared__ float sbuf[KT];
    __shared__ float red[256];
    const int q = blockIdx.x, b = blockIdx.y;
    const float* row = S + ((size_t)b * LQ + q) * KTP;
    h16* wh = Wh + ((size_t)b * LQ + q) * KT;
    const int valid = KC + q + 1;
    const int tid = threadIdx.x;

    float m = -1e30f;
    for (int c = tid; c < valid; c += 256) m = fmaxf(m, row[c] * scale);
    red[tid] = m; __syncthreads();
    for (int s = 128; s > 0; s >>= 1) { if (tid < s) red[tid] = fmaxf(red[tid], red[tid + s]); __syncthreads(); }
    m = red[0]; __syncthreads();

    float sum = 0.f;
    for (int c = tid; c < valid; c += 256) {
        float e = __expf(row[c] * scale - m);
        sbuf[c] = e;
        sum += e;
    }
    red[tid] = sum; __syncthreads();
    for (int s = 128; s > 0; s >>= 1) { if (tid < s) red[tid] += red[tid + s]; __syncthreads(); }
    const float inv = 1.f / red[0];
    __syncthreads();

    for (int c = tid; c < KT; c += 256)
        wh[c] = __float2half_rn((c < valid) ? sbuf[c] * inv : 0.f);
}

// ---------------------------------------------------------------------------
// kernel_launch — R12 graph structure (known-good):
//   s0(default): conversions -> Q proj -> (wait K) S -> softmax ->
//                (wait V) AV -> O
//   s1: cachek + K proj        s2: cachev + V^T proj (overlaps S/softmax)
// ---------------------------------------------------------------------------
extern "C" void kernel_launch(void* const* d_in, const int* in_sizes, int n_in,
                              void* d_out, int out_size)
{
    const float* chunk    = (const float*)d_in[0];
    const float* cached_k = (const float*)d_in[1];
    const float* cached_v = (const float*)d_in[2];
    int wi = 3;
    while (wi < n_in && in_sizes[wi] != DIMN * DIMN) wi++;
    const float* Wq = (const float*)d_in[wi + 0];
    const float* bq = (const float*)d_in[wi + 1];
    const float* Wk = (const float*)d_in[wi + 2];
    const float* bk = (const float*)d_in[wi + 3];
    const float* Wv = (const float*)d_in[wi + 4];
    const float* bv = (const float*)d_in[wi + 5];
    const float* Wo = (const float*)d_in[wi + 6];
    const float* bo = (const float*)d_in[wi + 7];
    float* out = (float*)d_out;

    h16 *ch, *wqh, *wkh, *wvh, *woh, *qh, *kh, *vh, *phh, *ahh;
    float* s;
    cudaGetSymbolAddress((void**)&ch, g_ch);
    cudaGetSymbolAddress((void**)&wqh, g_wqh);
    cudaGetSymbolAddress((void**)&wkh, g_wkh);
    cudaGetSymbolAddress((void**)&wvh, g_wvh);
    cudaGetSymbolAddress((void**)&woh, g_woh);
    cudaGetSymbolAddress((void**)&qh, g_qh);
    cudaGetSymbolAddress((void**)&kh, g_kh);
    cudaGetSymbolAddress((void**)&vh, g_vh);
    cudaGetSymbolAddress((void**)&s, g_s);
    cudaGetSymbolAddress((void**)&phh, g_ph);
    cudaGetSymbolAddress((void**)&ahh, g_ah);

    cudaFuncSetAttribute(gemm_mma<1,1,0>, cudaFuncAttributeMaxDynamicSharedMemorySize, SMEM_MMA);
    cudaFuncSetAttribute(gemm_mma<1,2,0>, cudaFuncAttributeMaxDynamicSharedMemorySize, SMEM_MMA);
    cudaFuncSetAttribute(gemm_mma<0,0,1>, cudaFuncAttributeMaxDynamicSharedMemorySize, SMEM_MMA);
    cudaFuncSetAttribute(gemm_mma<1,0,2>, cudaFuncAttributeMaxDynamicSharedMemorySize, SMEM_MMA);
    cudaFuncSetAttribute(gemm_mma<0,1,0>, cudaFuncAttributeMaxDynamicSharedMemorySize, SMEM_MMA);

    // one-time host-side handles (no device memory involved)
    static cudaStream_t s1 = nullptr, s2 = nullptr;
    static cudaEvent_t e0 = nullptr, eK = nullptr, eV = nullptr;
    if (s1 == nullptr) {
        cudaStreamCreateWithFlags(&s1, cudaStreamNonBlocking);
        cudaStreamCreateWithFlags(&s2, cudaStreamNonBlocking);
        cudaEventCreateWithFlags(&e0, cudaEventDisableTiming);
        cudaEventCreateWithFlags(&eK, cudaEventDisableTiming);
        cudaEventCreateWithFlags(&eV, cudaEventDisableTiming);
    }

    const float scale = (float)(1.0 / sqrt((double)DIMN));

    // --- conversions on the capture (default) stream
    {
        size_t n4 = (size_t)BATCH * LQ * DIMN / 4;
        round_kernel<<<(unsigned)((n4 + 255) / 256), 256>>>(chunk, ch, n4);
        size_t w4 = (size_t)DIMN * DIMN / 4;
        unsigned wg = (unsigned)((w4 + 255) / 256);
        round4_kernel<<<dim3(wg, 4), 256>>>(Wq, Wk, Wv, Wo, wqh, wkh, wvh, woh, w4);
    }
    cudaEventRecord(e0, 0);
    cudaStreamWaitEvent(s1, e0, 0);
    cudaStreamWaitEvent(s2, e0, 0);

    // --- s1: cached K + K projection
    {
        size_t ck4 = (size_t)BATCH * KC * DIMN / 4;
        cachek_kernel<<<(unsigned)((ck4 + 255) / 256), 256, 0, s1>>>(cached_k);
        gemm_mma<1,1,0><<<dim3(DIMN / BNT, LQ / BMT, BATCH), 256, SMEM_MMA, s1>>>(
            ch, wkh, bk, nullptr, kh + (size_t)KC * DIMN,
            DIMN, DIMN, DIMN, DIMN,
            (long long)LQ * DIMN, 0, (long long)KTP * DIMN);
        cudaEventRecord(eK, s1);
    }

    // --- s2: cached V + V^T projection
    {
        cachev_kernel<<<dim3(KC / 32, DIMN / 32, BATCH), dim3(32, 8), 0, s2>>>(cached_v);
        gemm_mma<1,2,0><<<dim3(LQ / BNT, DIMN / BMT, BATCH), 256, SMEM_MMA, s2>>>(
            wvh, ch, bv, nullptr, vh + KC,
            DIMN, DIMN, DIMN, KT,
            0, (long long)LQ * DIMN, (long long)DIMN * KT);
        cudaEventRecord(eV, s2);
    }

    // --- s0: Q projection
    gemm_mma<1,1,0><<<dim3(DIMN / BNT, (BATCH * LQ) / BMT, 1), 256, SMEM_MMA>>>(
        ch, wqh, bq, nullptr, qh,
        DIMN, DIMN, DIMN, DIMN, 0, 0, 0);

    // join K, then S = Q @ K^T (masked + pad tiles skipped)
    cudaStreamWaitEvent(0, eK, 0);
    gemm_mma<0,0,1><<<dim3(KTP / BNT, LQ / BMT, BATCH), 256, SMEM_MMA>>>(
        qh, kh, nullptr, s, nullptr,
        DIMN, DIMN, DIMN, KTP,
        (long long)LQ * DIMN, (long long)KTP * DIMN, (long long)LQ * KTP);

    // masked softmax -> fp16 weights
    softmax_kernel<<<dim3(LQ, BATCH), 256>>>(s, phh, scale);

    // join V, then attended = P @ V (K loop clamped, heavy rows first)
    cudaStreamWaitEvent(0, eV, 0);
    gemm_mma<1,0,2><<<dim3(DIMN / BNT, LQ / BMT, BATCH), 256, SMEM_MMA>>>(
        phh, vh, nullptr, nullptr, ahh,
        KT, KT, KT, DIMN,
        (long long)LQ * KT, (long long)DIMN * KT, (long long)LQ * DIMN);

    // output projection: attended @ Wo^T + bo -> fp32 out
    gemm_mma<0,1,0><<<dim3(DIMN / BNT, (BATCH * LQ) / BMT, 1), 256, SMEM_MMA>>>(
        ahh, woh, bo, out, nullptr,
        DIMN, DIMN, DIMN, DIMN, 0, 0, 0);
}

// round 17
// speedup vs baseline: 1.5685x; 1.0031x over previous
#include <cuda_runtime.h>
#include <cuda_fp16.h>
#include <math.h>
#include <stdint.h>

#define DIMN 2048
#define BATCH 4
#define LQ    4096
#define KC    576
#define KT    4672          // KC + LQ
#define KTP   4864          // padded N for the S GEMM (38*128)

typedef __half h16;

// ---------------------------------------------------------------------------
// Scratch (__device__ globals — zero-initialized; K rows [KT,KTP) stay 0)
// Fully single-pass fp16 scheme (calibrated error ~6e-4 < 1e-3).
// ---------------------------------------------------------------------------
__device__ h16 g_ch [(size_t)BATCH*LQ*DIMN];   // chunk (fp16)
__device__ h16 g_wqh[(size_t)DIMN*DIMN];
__device__ h16 g_wkh[(size_t)DIMN*DIMN];
__device__ h16 g_wvh[(size_t)DIMN*DIMN];
__device__ h16 g_woh[(size_t)DIMN*DIMN];
__device__ h16 g_qh [(size_t)BATCH*LQ*DIMN];
__device__ h16 g_kh [(size_t)BATCH*KTP*DIMN];
__device__ h16 g_vh [(size_t)BATCH*DIMN*KT];   // V^T [b][d][kt]
__device__ float g_s [(size_t)BATCH*LQ*KTP];
__device__ h16 g_ph [(size_t)BATCH*LQ*KT];
__device__ h16 g_ah [(size_t)BATCH*LQ*DIMN];

// ---------------------------------------------------------------------------
// helpers
// ---------------------------------------------------------------------------
__device__ __forceinline__ uint32_t s2u(const void* p) {
    uint32_t a;
    asm("{ .reg .u64 t; cvta.to.shared.u64 t, %1; cvt.u32.u64 %0, t; }" : "=r"(a) : "l"(p));
    return a;
}
__device__ __forceinline__ void cpa16(uint32_t d, const void* s) {
    asm volatile("cp.async.cg.shared.global [%0], [%1], 16;" :: "r"(d), "l"(s));
}
#define CP_COMMIT() asm volatile("cp.async.commit_group;" ::: "memory")
#define CP_WAIT1()  asm volatile("cp.async.wait_group 1;" ::: "memory")
#define CP_WAIT0()  asm volatile("cp.async.wait_group 0;" ::: "memory")

#define LDSM4(r, a) \
    asm volatile("ldmatrix.sync.aligned.m8n8.x4.shared.b16 {%0,%1,%2,%3}, [%4];" \
                 : "=r"((r)[0]), "=r"((r)[1]), "=r"((r)[2]), "=r"((r)[3]) : "r"(a))

__device__ __forceinline__ void mma16816(float* d, const uint32_t* a,
                                         uint32_t b0, uint32_t b1) {
    asm volatile(
        "mma.sync.aligned.m16n8k16.row.col.f32.f16.f16.f32 "
        "{%0,%1,%2,%3}, {%4,%5,%6,%7}, {%8,%9}, {%0,%1,%2,%3};"
        : "+f"(d[0]), "+f"(d[1]), "+f"(d[2]), "+f"(d[3])
        : "r"(a[0]), "r"(a[1]), "r"(a[2]), "r"(a[3]), "r"(b0), "r"(b1));
}

__device__ __forceinline__ uint32_t round2h(float x0, float x1) {
    __half2 hp = __floats2half2_rn(x0, x1);
    return *reinterpret_cast<uint32_t*>(&hp);
}

// ---------------------------------------------------------------------------
// fp16 single-pass mma.sync GEMM: C tile 128x128, BK=32, 3-stage cp.async
// pipeline, ONE __syncthreads per k-chunk. Fragments for BOTH ks steps are
// loaded up-front into separate register buffers (no LDSM<->mma register WAR
// hazard; the LDSM chain pipelines under the first mma group). fp32 accum.
// A[M,K], B[N,K] row-major (NT).
// OUTM: 0 fp32 out, 1 fp16 out.
// BIASM: 0 none, 1 bias[col], 2 bias[row]
// TRI:  0 none, 1 = skip block if col0 >= KC+row0+BMT or col0 >= KT (S GEMM),
//       2 = clamp K loop to KC+row0+BMT (AV GEMM; heavy rows scheduled first)
// ---------------------------------------------------------------------------
#define BMT 128
#define BNT 128
#define BKT 32
#define APAD 40                          // fp16 row stride (32+8) -> 80B
#define TILE_B (128 * APAD * 2)          // 10240 bytes per tile
#define STAGE_B (2 * TILE_B)             // A|B = 20480
#define SMEM_MMA (3 * STAGE_B)           // 61440 bytes (3 stages) -> 2 CTAs/SM

template<int OUTM, int BIASM, int TRI>
__global__ __launch_bounds__(256, 2)
void gemm_mma(const h16* __restrict__ Ah,
              const h16* __restrict__ Bh,
              const float* __restrict__ bias,
              float* __restrict__ Cf, h16* __restrict__ Ch,
              int K, int lda, int ldb, int ldc,
              long long sA, long long sB, long long sC)
{
    // TRI==2: reverse row order so the heaviest (longest-K) CTAs start first
    const int row0 = (TRI == 2 ? (int)(gridDim.y - 1 - blockIdx.y) : (int)blockIdx.y) * BMT;
    const int col0 = blockIdx.x * BNT;
    if (TRI == 1 && (col0 >= KC + row0 + BMT || col0 >= KT)) return; // masked / pad tile

    extern __shared__ h16 sm[];
    const uint32_t smb = s2u(sm);
    const int tid  = threadIdx.x;
    const int lane = tid & 31, warp = tid >> 5;
    const int wm = warp & 1, wn = warp >> 1;    // warp grid 2 (M) x 4 (N)
    const size_t zA = (size_t)blockIdx.z * sA;
    const size_t zB = (size_t)blockIdx.z * sB;
    const size_t zC = (size_t)blockIdx.z * sC;

    int kchunks = K / BKT;
    if (TRI == 2) {
        int lim = (KC + row0 + BMT) / BKT;      // multiple of 32 by construction
        if (lim < kchunks) kchunks = lim;
    }

    // cp.async mapping: rows (tid>>2) and (tid>>2)+64, 16B chunk (tid&3)*8
    const int lrow = tid >> 2;
    const int lcol = (tid & 3) * 8;
    const uint32_t o1 = (lrow * APAD + lcol) * 2;
    const uint32_t o2 = ((lrow + 64) * APAD + lcol) * 2;

    auto issue = [&](int kc, int st) {
        const size_t ao = zA + (size_t)(row0 + lrow) * lda + (size_t)kc * BKT + lcol;
        const size_t bo = zB + (size_t)(col0 + lrow) * ldb + (size_t)kc * BKT + lcol;
        const uint32_t base = smb + st * STAGE_B;
        cpa16(base + o1,          Ah + ao);
        cpa16(base + o2,          Ah + ao + (size_t)64 * lda);
        cpa16(base + TILE_B + o1, Bh + bo);
        cpa16(base + TILE_B + o2, Bh + bo + (size_t)64 * ldb);
    };

    float acc[4][4][4];
#pragma unroll
    for (int i = 0; i < 4; i++)
#pragma unroll
        for (int j = 0; j < 4; j++)
#pragma unroll
            for (int e = 0; e < 4; e++) acc[i][j][e] = 0.f;

    // ldmatrix per-thread address components
    const int am = wm * 64 + (lane & 15);
    const int ak = (lane >> 4) * 8;
    const int bn = wn * 32 + (lane & 15);

    // prologue: fill 2 of the 3 stages
    issue(0, 0); CP_COMMIT();
    if (kchunks > 1) { issue(1, 1); CP_COMMIT(); }

    int st = 0;
    for (int kc = 0; kc < kchunks; ++kc) {
        if (kc + 1 < kchunks) CP_WAIT1(); else CP_WAIT0();
        __syncthreads();   // also covers the WAR hazard for stage (kc+2)%3

        if (kc + 2 < kchunks) {
            int st2 = st + 2; if (st2 >= 3) st2 -= 3;
            issue(kc + 2, st2);
            CP_COMMIT();
        }

        const uint32_t ah_ = smb + st * STAGE_B;
        const uint32_t bh_ = ah_ + TILE_B;

        // load fragments for BOTH ks steps up-front (independent registers)
        uint32_t afA[4][4], bhA[2][4], afB[4][4], bhB[2][4];
#pragma unroll
        for (int mt = 0; mt < 4; mt++)
            LDSM4(afA[mt], ah_ + (((am + mt * 16) * APAD) + ak) * 2);
#pragma unroll
        for (int pr = 0; pr < 2; pr++)
            LDSM4(bhA[pr], bh_ + (((bn + pr * 16) * APAD) + ak) * 2);
#pragma unroll
        for (int mt = 0; mt < 4; mt++)
            LDSM4(afB[mt], ah_ + (((am + mt * 16) * APAD) + 16 + ak) * 2);
#pragma unroll
        for (int pr = 0; pr < 2; pr++)
            LDSM4(bhB[pr], bh_ + (((bn + pr * 16) * APAD) + 16 + ak) * 2);

        // ks = 0 (overlaps with the tail of the LDSM chain)
#pragma unroll
        for (int mt = 0; mt < 4; mt++)
#pragma unroll
            for (int nt = 0; nt < 4; nt++)
                mma16816(acc[mt][nt], afA[mt],
                         bhA[nt >> 1][nt & 1], bhA[nt >> 1][(nt & 1) + 2]);
        // ks = 1
#pragma unroll
        for (int mt = 0; mt < 4; mt++)
#pragma unroll
            for (int nt = 0; nt < 4; nt++)
                mma16816(acc[mt][nt], afB[mt],
                         bhB[nt >> 1][nt & 1], bhB[nt >> 1][(nt & 1) + 2]);

        if (++st == 3) st = 0;
    }

    // epilogue
    const int crow = lane >> 2;
    const int ccol = (lane & 3) * 2;
#pragma unroll
    for (int mt = 0; mt < 4; mt++) {
        const size_t r0g = (size_t)row0 + wm * 64 + mt * 16 + crow;
#pragma unroll
        for (int nt = 0; nt < 4; nt++) {
            const int cg = col0 + wn * 32 + nt * 8 + ccol;
            float v0 = acc[mt][nt][0], v1 = acc[mt][nt][1];
            float v2 = acc[mt][nt][2], v3 = acc[mt][nt][3];
            if (BIASM == 1) {
                const float b0 = bias[cg], b1 = bias[cg + 1];
                v0 += b0; v1 += b1; v2 += b0; v3 += b1;
            }
            if (BIASM == 2) {
                const float b0 = bias[r0g], b1 = bias[r0g + 8];
                v0 += b0; v1 += b0; v2 += b1; v3 += b1;
            }
            if (OUTM == 0) {
                *reinterpret_cast<float2*>(&Cf[zC + r0g * ldc + cg])       = make_float2(v0, v1);
                *reinterpret_cast<float2*>(&Cf[zC + (r0g + 8) * ldc + cg]) = make_float2(v2, v3);
            } else {
                *reinterpret_cast<uint32_t*>(&Ch[zC + r0g * ldc + cg])       = round2h(v0, v1);
                *reinterpret_cast<uint32_t*>(&Ch[zC + (r0g + 8) * ldc + cg]) = round2h(v2, v3);
            }
        }
    }
}

// ---------------------------------------------------------------------------
// Elementwise fp32 -> fp16 (single tensor)
// ---------------------------------------------------------------------------
__global__ void round_kernel(const float* __restrict__ src, h16* __restrict__ h, size_t n4)
{
    size_t i = (size_t)blockIdx.x * blockDim.x + threadIdx.x;
    if (i >= n4) return;
    float4 v = reinterpret_cast<const float4*>(src)[i];
    reinterpret_cast<uint2*>(h)[i] = make_uint2(round2h(v.x, v.y), round2h(v.z, v.w));
}

// Fused fp32 -> fp16 for the four weight matrices (blockIdx.y selects tensor)
__global__ void round4_kernel(const float* __restrict__ w0, const float* __restrict__ w1,
                              const float* __restrict__ w2, const float* __restrict__ w3,
                              h16* __restrict__ d0, h16* __restrict__ d1,
                              h16* __restrict__ d2, h16* __restrict__ d3,
                              size_t n4)
{
    size_t i = (size_t)blockIdx.x * blockDim.x + threadIdx.x;
    if (i >= n4) return;
    const float* src = (blockIdx.y == 0) ? w0 : (blockIdx.y == 1) ? w1
                     : (blockIdx.y == 2) ? w2 : w3;
    h16* dst = (blockIdx.y == 0) ? d0 : (blockIdx.y == 1) ? d1
             : (blockIdx.y == 2) ? d2 : d3;
    float4 v = reinterpret_cast<const float4*>(src)[i];
    reinterpret_cast<uint2*>(dst)[i] = make_uint2(round2h(v.x, v.y), round2h(v.z, v.w));
}

// cached_k [B,KC,D] -> fp16 into front rows of g_kh (row stride KTP per batch)
__global__ void cachek_kernel(const float* __restrict__ ck)
{
    const size_t per = (size_t)KC * DIMN / 4;
    size_t i = (size_t)blockIdx.x * blockDim.x + threadIdx.x;
    if (i >= BATCH * per) return;
    size_t b = i / per, r = i - b * per;
    float4 v = reinterpret_cast<const float4*>(ck)[i];
    size_t dst = b * ((size_t)KTP * DIMN / 4) + r;
    reinterpret_cast<uint2*>(g_kh)[dst] = make_uint2(round2h(v.x, v.y), round2h(v.z, v.w));
}

// cached_v [B,KC,D] -> transposed into g_vh [B,D,KT] cols [0,KC)
__global__ void cachev_kernel(const float* __restrict__ cv)
{
    __shared__ float t[32][33];
    const int b = blockIdx.z;
    const int r0 = blockIdx.x * 32;   // kc
    const int c0 = blockIdx.y * 32;   // d
    const int tx = threadIdx.x, ty0 = threadIdx.y;
#pragma unroll
    for (int s = 0; s < 4; s++) {
        int ty = ty0 + s * 8;
        t[ty][tx] = cv[((size_t)b * KC + r0 + ty) * DIMN + c0 + tx];
    }
    __syncthreads();
#pragma unroll
    for (int s = 0; s < 4; s++) {
        int ty = ty0 + s * 8;
        size_t o = ((size_t)b * DIMN + c0 + ty) * KT + r0 + tx;
        g_vh[o] = __float2half_rn(t[tx][ty]);
    }
}

// ---------------------------------------------------------------------------
// Masked softmax: row q sees [0, KC+q+1); emits fp16 weights (0 beyond).
// ---------------------------------------------------------------------------
__global__ void softmax_kernel(const float* __restrict__ S, h16* __restrict__ Wh,
                               float scale)
{
    __shared__ float sbuf[KT];
    __shared__ float red[256];
    const int q = blockIdx.x, b = blockIdx.y;
    const float* row = S + ((size_t)b * LQ + q) * KTP;
    h16* wh = Wh + ((size_t)b * LQ + q) * KT;
    const int valid = KC + q + 1;
    const int tid = threadIdx.x;

    float m = -1e30f;
    for (int c = tid; c < valid; c += 256) m = fmaxf(m, row[c] * scale);
    red[tid] = m; __syncthreads();
    for (int s = 128; s > 0; s >>= 1) { if (tid < s) red[tid] = fmaxf(red[tid], red[tid + s]); __syncthreads(); }
    m = red[0]; __syncthreads();

    float sum = 0.f;
    for (int c = tid; c < valid; c += 256) {
        float e = __expf(row[c] * scale - m);
        sbuf[c] = e;
        sum += e;
    }
    red[tid] = sum; __syncthreads();
    for (int s = 128; s > 0; s >>= 1) { if (tid < s) red[tid] += red[tid + s]; __syncthreads(); }
    const float inv = 1.f / red[0];
    __syncthreads();

    for (int c = tid; c < KT; c += 256)
        wh[c] = __float2half_rn((c < valid) ? sbuf[c] * inv : 0.f);
}

// ---------------------------------------------------------------------------
// kernel_launch — R12 graph structure (known-good):
//   s0(default): conversions -> Q proj -> (wait K) S -> softmax ->
//                (wait V) AV -> O
//   s1: cachek + K proj        s2: cachev + V^T proj (overlaps S/softmax)
// ---------------------------------------------------------------------------
extern "C" void kernel_launch(void* const* d_in, const int* in_sizes, int n_in,
                              void* d_out, int out_size)
{
    const float* chunk    = (const float*)d_in[0];
    const float* cached_k = (const float*)d_in[1];
    const float* cached_v = (const float*)d_in[2];
    int wi = 3;
    while (wi < n_in && in_sizes[wi] != DIMN * DIMN) wi++;
    const float* Wq = (const float*)d_in[wi + 0];
    const float* bq = (const float*)d_in[wi + 1];
    const float* Wk = (const float*)d_in[wi + 2];
    const float* bk = (const float*)d_in[wi + 3];
    const float* Wv = (const float*)d_in[wi + 4];
    const float* bv = (const float*)d_in[wi + 5];
    const float* Wo = (const float*)d_in[wi + 6];
    const float* bo = (const float*)d_in[wi + 7];
    float* out = (float*)d_out;

    h16 *ch, *wqh, *wkh, *wvh, *woh, *qh, *kh, *vh, *phh, *ahh;
    float* s;
    cudaGetSymbolAddress((void**)&ch, g_ch);
    cudaGetSymbolAddress((void**)&wqh, g_wqh);
    cudaGetSymbolAddress((void**)&wkh, g_wkh);
    cudaGetSymbolAddress((void**)&wvh, g_wvh);
    cudaGetSymbolAddress((void**)&woh, g_woh);
    cudaGetSymbolAddress((void**)&qh, g_qh);
    cudaGetSymbolAddress((void**)&kh, g_kh);
    cudaGetSymbolAddress((void**)&vh, g_vh);
    cudaGetSymbolAddress((void**)&s, g_s);
    cudaGetSymbolAddress((void**)&phh, g_ph);
    cudaGetSymbolAddress((void**)&ahh, g_ah);

    cudaFuncSetAttribute(gemm_mma<1,1,0>, cudaFuncAttributeMaxDynamicSharedMemorySize, SMEM_MMA);
    cudaFuncSetAttribute(gemm_mma<1,2,0>, cudaFuncAttributeMaxDynamicSharedMemorySize, SMEM_MMA);
    cudaFuncSetAttribute(gemm_mma<0,0,1>, cudaFuncAttributeMaxDynamicSharedMemorySize, SMEM_MMA);
    cudaFuncSetAttribute(gemm_mma<1,0,2>, cudaFuncAttributeMaxDynamicSharedMemorySize, SMEM_MMA);
    cudaFuncSetAttribute(gemm_mma<0,1,0>, cudaFuncAttributeMaxDynamicSharedMemorySize, SMEM_MMA);

    // one-time host-side handles (no device memory involved)
    static cudaStream_t s1 = nullptr, s2 = nullptr;
    static cudaEvent_t e0 = nullptr, eK = nullptr, eV = nullptr;
    if (s1 == nullptr) {
        cudaStreamCreateWithFlags(&s1, cudaStreamNonBlocking);
        cudaStreamCreateWithFlags(&s2, cudaStreamNonBlocking);
        cudaEventCreateWithFlags(&e0, cudaEventDisableTiming);
        cudaEventCreateWithFlags(&eK, cudaEventDisableTiming);
        cudaEventCreateWithFlags(&eV, cudaEventDisableTiming);
    }

    const float scale = (float)(1.0 / sqrt((double)DIMN));

    // --- conversions on the capture (default) stream
    {
        size_t n4 = (size_t)BATCH * LQ * DIMN / 4;
        round_kernel<<<(unsigned)((n4 + 255) / 256), 256>>>(chunk, ch, n4);
        size_t w4 = (size_t)DIMN * DIMN / 4;
        unsigned wg = (unsigned)((w4 + 255) / 256);
        round4_kernel<<<dim3(wg, 4), 256>>>(Wq, Wk, Wv, Wo, wqh, wkh, wvh, woh, w4);
    }
    cudaEventRecord(e0, 0);
    cudaStreamWaitEvent(s1, e0, 0);
    cudaStreamWaitEvent(s2, e0, 0);

    // --- s1: cached K + K projection
    {
        size_t ck4 = (size_t)BATCH * KC * DIMN / 4;
        cachek_kernel<<<(unsigned)((ck4 + 255) / 256), 256, 0, s1>>>(cached_k);
        gemm_mma<1,1,0><<<dim3(DIMN / BNT, LQ / BMT, BATCH), 256, SMEM_MMA, s1>>>(
            ch, wkh, bk, nullptr, kh + (size_t)KC * DIMN,
            DIMN, DIMN, DIMN, DIMN,
            (long long)LQ * DIMN, 0, (long long)KTP * DIMN);
        cudaEventRecord(eK, s1);
    }

    // --- s2: cached V + V^T projection
    {
        cachev_kernel<<<dim3(KC / 32, DIMN / 32, BATCH), dim3(32, 8), 0, s2>>>(cached_v);
        gemm_mma<1,2,0><<<dim3(LQ / BNT, DIMN / BMT, BATCH), 256, SMEM_MMA, s2>>>(
            wvh, ch, bv, nullptr, vh + KC,
            DIMN, DIMN, DIMN, KT,
            0, (long long)LQ * DIMN, (long long)DIMN * KT);
        cudaEventRecord(eV, s2);
    }

    // --- s0: Q projection
    gemm_mma<1,1,0><<<dim3(DIMN / BNT, (BATCH * LQ) / BMT, 1), 256, SMEM_MMA>>>(
        ch, wqh, bq, nullptr, qh,
        DIMN, DIMN, DIMN, DIMN, 0, 0, 0);

    // join K, then S = Q @ K^T (masked + pad tiles skipped)
    cudaStreamWaitEvent(0, eK, 0);
    gemm_mma<0,0,1><<<dim3(KTP / BNT, LQ / BMT, BATCH), 256, SMEM_MMA>>>(
        qh, kh, nullptr, s, nullptr,
        DIMN, DIMN, DIMN, KTP,
        (long long)LQ * DIMN, (long long)KTP * DIMN, (long long)LQ * KTP);

    // masked softmax -> fp16 weights
    softmax_kernel<<<dim3(LQ, BATCH), 256>>>(s, phh, scale);

    // join V, then attended = P @ V (K loop clamped, heavy rows first)
    cudaStreamWaitEvent(0, eV, 0);
    gemm_mma<1,0,2><<<dim3(DIMN / BNT, LQ / BMT, BATCH), 256, SMEM_MMA>>>(
        phh, vh, nullptr, nullptr, ahh,
        KT, KT, KT, DIMN,
        (long long)LQ * KT, (long long)DIMN * KT, (long long)LQ * DIMN);

    // output projection: attended @ Wo^T + bo -> fp32 out
    gemm_mma<0,1,0><<<dim3(DIMN / BNT, (BATCH * LQ) / BMT, 1), 256, SMEM_MMA>>>(
        ahh, woh, bo, out, nullptr,
        DIMN, DIMN, DIMN, DIMN, 0, 0, 0);
}